// round 2
// baseline (speedup 1.0000x reference)
#include <cuda_runtime.h>
#include <cstdint>
#include <cstddef>

// Problem constants
#define Bn 64
#define Sq 512
#define Dk 1024
#define Uo 4096
#define Ex 16

// Tiling
#define BM 128
#define BN 128
#define BK 32
#define NK (Dk / BK)        // 32 K-tiles
#define NTHREADS 256
#define STAGES 3

// SMEM strides (in floats) chosen for conflict-free fragment LDS
#define SA_STRIDE 36        // A: [BM][36]   -> bank = (4r + c) % 32, all distinct
#define SB_STRIDE 136       // B: [BK][136]  -> bank = (8c + r) % 32, all distinct
#define A_FLOATS (BM * SA_STRIDE)            // 4608
#define B_FLOATS (BK * SB_STRIDE)            // 4352
#define STG_BYTES ((A_FLOATS + B_FLOATS) * 4)  // 35840
#define A_BYTES (A_FLOATS * 4)               // 18432
#define BIAS_OFF (STAGES * STG_BYTES)        // 107520
#define SMEM_REQ (BIAS_OFF + BN * 4)         // 108032

// Device scratch: tf32-rounded copies of ws and x (no runtime allocation)
__device__ uint32_t g_ws32[(size_t)Ex * Dk * Uo];   // [e][k][n], 256 MB
__device__ uint32_t g_x32[(size_t)Bn * Sq * Dk];    // [b][m][k], 128 MB

// ---------------- helpers ----------------
__device__ __forceinline__ uint32_t smem_u32(const void* p) {
    uint32_t a;
    asm("{ .reg .u64 t; cvta.to.shared.u64 t, %1; cvt.u32.u64 %0, t; }"
        : "=r"(a) : "l"(p));
    return a;
}

__device__ __forceinline__ uint32_t f32_to_tf32(float f) {
    uint32_t u;
    asm("cvt.rna.tf32.f32 %0, %1;" : "=r"(u) : "f"(f));
    return u;
}

__device__ __forceinline__ void cp16(uint32_t saddr, const void* g) {
    asm volatile("cp.async.cg.shared.global [%0], [%1], 16;" :: "r"(saddr), "l"(g));
}
__device__ __forceinline__ void cp_commit() {
    asm volatile("cp.async.commit_group;" ::: "memory");
}
template <int N>
__device__ __forceinline__ void cp_wait() {
    asm volatile("cp.async.wait_group %0;" :: "n"(N) : "memory");
}

__device__ __forceinline__ void mma_tf32(float* d, const uint32_t* a, const uint32_t* b) {
    asm volatile(
        "mma.sync.aligned.m16n8k8.row.col.f32.tf32.tf32.f32 "
        "{%0,%1,%2,%3}, {%4,%5,%6,%7}, {%8,%9}, {%0,%1,%2,%3};"
        : "+f"(d[0]), "+f"(d[1]), "+f"(d[2]), "+f"(d[3])
        : "r"(a[0]), "r"(a[1]), "r"(a[2]), "r"(a[3]), "r"(b[0]), "r"(b[1]));
}

// ---------------- pre-pass: fp32 -> tf32(rna) bit copies ----------------
__global__ void __launch_bounds__(256) cvt_tf32_kernel(const float4* __restrict__ src,
                                                       uint4* __restrict__ dst, size_t n4) {
    size_t i = (size_t)blockIdx.x * blockDim.x + threadIdx.x;
    size_t stride = (size_t)gridDim.x * blockDim.x;
    for (; i < n4; i += stride) {
        float4 v = src[i];
        uint4 o;
        o.x = f32_to_tf32(v.x); o.y = f32_to_tf32(v.y);
        o.z = f32_to_tf32(v.z); o.w = f32_to_tf32(v.w);
        dst[i] = o;
    }
}

// ---------------- main GEMM ----------------
__global__ void __launch_bounds__(NTHREADS)
indexed_dense_gemm(const float* __restrict__ bs, const int* __restrict__ index,
                   float* __restrict__ out) {
    extern __shared__ char smem[];
    const uint32_t sbase = smem_u32(smem);
    float* const smf = reinterpret_cast<float*>(smem);

    const int tid   = threadIdx.x;
    const int batch = blockIdx.z;
    const int m0    = blockIdx.y * BM;
    const int n0    = blockIdx.x * BN;
    const int e     = index[batch];

    // bias tile -> smem
    if (tid < BN)
        smf[BIAS_OFF / 4 + tid] = bs[(size_t)e * Uo + n0 + tid];

    const uint32_t* __restrict__ xg =
        g_x32 + ((size_t)batch * Sq + m0) * Dk;
    const uint32_t* __restrict__ wg =
        g_ws32 + (size_t)e * Dk * Uo + n0;

    // per-thread load coordinates
    const int am  = tid >> 1;          // 0..127 (A row)
    const int akg = (tid & 1) * 4;     // A col group (floats)
    const int bk  = tid >> 3;          // 0..31  (B row = k)
    const int bng = (tid & 7) * 4;     // B col group (floats)

    const uint32_t a_s0 = sbase + (uint32_t)(am * SA_STRIDE + akg) * 4;
    const uint32_t b_s0 = sbase + A_BYTES + (uint32_t)(bk * SB_STRIDE + bng) * 4;

    auto load_stage = [&](int kt, int s) {
        const uint32_t so = (uint32_t)s * STG_BYTES;
        const uint32_t* ag = xg + (size_t)am * Dk + kt * BK + akg;
        const uint32_t* bg = wg + (size_t)(kt * BK + bk) * Uo + bng;
#pragma unroll
        for (int j = 0; j < 4; j++)      // A: 4 x 16B, k step 8 floats
            cp16(a_s0 + so + j * 32, ag + j * 8);
#pragma unroll
        for (int j = 0; j < 4; j++)      // B: 4 x 16B, n step 32 floats
            cp16(b_s0 + so + j * 128, bg + j * 32);
    };

    // prologue: stages 0,1
    load_stage(0, 0); cp_commit();
    load_stage(1, 1); cp_commit();

    // warp tiling: 8 warps = 4 (m) x 2 (n); warp tile 32 x 64
    const int warp = tid >> 5;
    const int lane = tid & 31;
    const int wm   = (warp & 3) * 32;
    const int wn   = (warp >> 2) * 64;
    const int r    = lane >> 2;
    const int c    = lane & 3;

    float d[2][8][4];
#pragma unroll
    for (int mi = 0; mi < 2; mi++)
#pragma unroll
        for (int ni = 0; ni < 8; ni++)
#pragma unroll
            for (int j = 0; j < 4; j++) d[mi][ni][j] = 0.0f;

#pragma unroll 1
    for (int kt = 0; kt < NK; kt++) {
        cp_wait<1>();
        __syncthreads();

        if (kt + 2 < NK) load_stage(kt + 2, (kt + 2) % STAGES);
        cp_commit();   // commit every iteration (possibly empty) to keep group counting uniform

        const uint32_t* sa = reinterpret_cast<const uint32_t*>(
            smem + (size_t)(kt % STAGES) * STG_BYTES);
        const uint32_t* sb = sa + A_FLOATS;

#pragma unroll
        for (int ks = 0; ks < 4; ks++) {
            const int k = ks * 8;
            uint32_t a[2][4];
#pragma unroll
            for (int mi = 0; mi < 2; mi++) {
                const int row = wm + mi * 16 + r;
                a[mi][0] = sa[(size_t)row * SA_STRIDE + k + c];
                a[mi][1] = sa[(size_t)(row + 8) * SA_STRIDE + k + c];
                a[mi][2] = sa[(size_t)row * SA_STRIDE + k + c + 4];
                a[mi][3] = sa[(size_t)(row + 8) * SA_STRIDE + k + c + 4];
            }
            uint32_t b[8][2];
#pragma unroll
            for (int ni = 0; ni < 8; ni++) {
                const int col = wn + ni * 8 + r;
                b[ni][0] = sb[(size_t)(k + c) * SB_STRIDE + col];
                b[ni][1] = sb[(size_t)(k + c + 4) * SB_STRIDE + col];
            }
#pragma unroll
            for (int mi = 0; mi < 2; mi++)
#pragma unroll
                for (int ni = 0; ni < 8; ni++)
                    mma_tf32(d[mi][ni], a[mi], b[ni]);
        }
    }

    // epilogue: bias + relu + float2 stores
    const float* bias_s = smf + BIAS_OFF / 4 + wn;
#pragma unroll
    for (int mi = 0; mi < 2; mi++) {
#pragma unroll
        for (int rr = 0; rr < 2; rr++) {
            const int m = m0 + wm + mi * 16 + rr * 8 + r;
            float* op = out + ((size_t)batch * Sq + m) * Uo + n0 + wn;
#pragma unroll
            for (int ni = 0; ni < 8; ni++) {
                const int nl = ni * 8 + 2 * c;
                float2 v;
                v.x = fmaxf(d[mi][ni][2 * rr + 0] + bias_s[nl + 0], 0.0f);
                v.y = fmaxf(d[mi][ni][2 * rr + 1] + bias_s[nl + 1], 0.0f);
                *reinterpret_cast<float2*>(op + nl) = v;
            }
        }
    }
}

// ---------------- launch ----------------
extern "C" void kernel_launch(void* const* d_in, const int* in_sizes, int n_in,
                              void* d_out, int out_size) {
    const float* x     = (const float*)d_in[0];
    const float* ws    = (const float*)d_in[1];
    const float* bs    = (const float*)d_in[2];
    const int*   index = (const int*)d_in[3];
    float*       out   = (float*)d_out;
    (void)in_sizes; (void)n_in; (void)out_size;

    // resolve device-scratch addresses (no allocation; __device__ globals)
    uint32_t* ws32_ptr = nullptr;
    uint32_t* x32_ptr  = nullptr;
    cudaGetSymbolAddress((void**)&ws32_ptr, g_ws32);
    cudaGetSymbolAddress((void**)&x32_ptr, g_x32);

    // pre-pass: round ws and x to tf32 (rna) bit patterns
    const size_t ws_n4 = (size_t)Ex * Dk * Uo / 4;   // 16,777,216
    const size_t x_n4  = (size_t)Bn * Sq * Dk / 4;   //  8,388,608
    cvt_tf32_kernel<<<8192, 256>>>((const float4*)ws, (uint4*)ws32_ptr, ws_n4);
    cvt_tf32_kernel<<<4096, 256>>>((const float4*)x, (uint4*)x32_ptr, x_n4);

    static bool attr_set = false;
    if (!attr_set) {
        cudaFuncSetAttribute(indexed_dense_gemm,
                             cudaFuncAttributeMaxDynamicSharedMemorySize, SMEM_REQ);
        attr_set = true;
    }

    indexed_dense_gemm<<<dim3(Uo / BN, Sq / BM, Bn), NTHREADS, SMEM_REQ>>>(bs, index, out);
}

// round 3
// speedup vs baseline: 1.1326x; 1.1326x over previous
#include <cuda_runtime.h>
#include <cstdint>
#include <cstddef>

// Problem constants
#define Bn 64
#define Sq 512
#define Dk 1024
#define Uo 4096
#define Ex 16

// Tiling: CTA 128x256, warp 64x64 (8 warps = 2m x 4n), 256 threads
#define BM 128
#define BN 256
#define BK 32
#define NK (Dk / BK)        // 32 K-tiles
#define NTHREADS 256
#define STAGES 3

// SMEM strides (floats) chosen for conflict-free fragment LDS
#define SA_STRIDE 36        // A: [BM][36]   bank = (4r + c) % 32, distinct per warp-quad
#define SB_STRIDE 264       // B: [BK][264]  bank = (8c + 8ni + r) % 32, distinct
#define A_FLOATS (BM * SA_STRIDE)              // 4608
#define B_FLOATS (BK * SB_STRIDE)              // 8448
#define STG_BYTES ((A_FLOATS + B_FLOATS) * 4)  // 52224
#define A_BYTES (A_FLOATS * 4)                 // 18432
#define BIAS_OFF (STAGES * STG_BYTES)          // 156672
#define SMEM_REQ (BIAS_OFF + BN * 4)           // 157696

// Device scratch: tf32(rna)-rounded copies of ws and x
__device__ uint32_t g_ws32[(size_t)Ex * Dk * Uo];   // [e][k][n]
__device__ uint32_t g_x32[(size_t)Bn * Sq * Dk];    // [b][m][k]

// ---------------- helpers ----------------
__device__ __forceinline__ uint32_t smem_u32(const void* p) {
    uint32_t a;
    asm("{ .reg .u64 t; cvta.to.shared.u64 t, %1; cvt.u32.u64 %0, t; }"
        : "=r"(a) : "l"(p));
    return a;
}

__device__ __forceinline__ uint32_t f32_to_tf32(float f) {
    uint32_t u;
    asm("cvt.rna.tf32.f32 %0, %1;" : "=r"(u) : "f"(f));
    return u;
}

__device__ __forceinline__ void cp16(uint32_t saddr, const void* g) {
    asm volatile("cp.async.cg.shared.global [%0], [%1], 16;" :: "r"(saddr), "l"(g));
}
__device__ __forceinline__ void cp_commit() {
    asm volatile("cp.async.commit_group;" ::: "memory");
}
template <int N>
__device__ __forceinline__ void cp_wait() {
    asm volatile("cp.async.wait_group %0;" :: "n"(N) : "memory");
}

__device__ __forceinline__ void mma_tf32(float* d, const uint32_t* a, const uint32_t* b) {
    asm volatile(
        "mma.sync.aligned.m16n8k8.row.col.f32.tf32.tf32.f32 "
        "{%0,%1,%2,%3}, {%4,%5,%6,%7}, {%8,%9}, {%0,%1,%2,%3};"
        : "+f"(d[0]), "+f"(d[1]), "+f"(d[2]), "+f"(d[3])
        : "r"(a[0]), "r"(a[1]), "r"(a[2]), "r"(a[3]), "r"(b[0]), "r"(b[1]));
}

// ---------------- pre-pass: fp32 -> tf32(rna) bit copies ----------------
__global__ void __launch_bounds__(256) cvt_tf32_kernel(const float4* __restrict__ src,
                                                       uint4* __restrict__ dst, size_t n4) {
    size_t i = (size_t)blockIdx.x * blockDim.x + threadIdx.x;
    size_t stride = (size_t)gridDim.x * blockDim.x;
    for (; i < n4; i += stride) {
        float4 v = src[i];
        uint4 o;
        o.x = f32_to_tf32(v.x); o.y = f32_to_tf32(v.y);
        o.z = f32_to_tf32(v.z); o.w = f32_to_tf32(v.w);
        dst[i] = o;
    }
}

// ---------------- main GEMM ----------------
__global__ void __launch_bounds__(NTHREADS)
indexed_dense_gemm(const float* __restrict__ bs, const int* __restrict__ index,
                   float* __restrict__ out) {
    extern __shared__ char smem[];
    const uint32_t sbase = smem_u32(smem);
    float* const smf = reinterpret_cast<float*>(smem);

    const int tid   = threadIdx.x;
    const int batch = blockIdx.z;
    const int m0    = blockIdx.y * BM;
    const int n0    = blockIdx.x * BN;
    const int e     = index[batch];

    // bias tile -> smem (256 floats, one per thread)
    smf[BIAS_OFF / 4 + tid] = bs[(size_t)e * Uo + n0 + tid];

    const uint32_t* __restrict__ xg = g_x32 + ((size_t)batch * Sq + m0) * Dk;
    const uint32_t* __restrict__ wg = g_ws32 + (size_t)e * Dk * Uo + n0;

    // per-thread load coordinates
    const int am  = tid >> 1;          // A row 0..127
    const int akg = (tid & 1) * 4;     // A col group (floats)
    const int bk  = tid >> 3;          // B row (k) 0..31
    const int bng = (tid & 7) * 4;     // B col group (floats)

    const uint32_t a_s0 = sbase + (uint32_t)(am * SA_STRIDE + akg) * 4;
    const uint32_t b_s0 = sbase + A_BYTES + (uint32_t)(bk * SB_STRIDE + bng) * 4;

    auto load_stage = [&](int kt, int s) {
        const uint32_t so = (uint32_t)s * STG_BYTES;
        const uint32_t* ag = xg + (size_t)am * Dk + kt * BK + akg;
        const uint32_t* bg = wg + (size_t)(kt * BK + bk) * Uo + bng;
#pragma unroll
        for (int j = 0; j < 4; j++)       // A: 4 x 16B, k step 8 floats
            cp16(a_s0 + so + j * 32, ag + j * 8);
#pragma unroll
        for (int j = 0; j < 8; j++)       // B: 8 x 16B, n step 32 floats
            cp16(b_s0 + so + j * 128, bg + j * 32);
    };

    // prologue: stages 0,1
    load_stage(0, 0); cp_commit();
    load_stage(1, 1); cp_commit();

    // warp tiling: 8 warps = 2 (m) x 4 (n); warp tile 64 x 64
    const int warp = tid >> 5;
    const int lane = tid & 31;
    const int wm   = (warp >> 2) * 64;
    const int wn   = (warp & 3) * 64;
    const int r    = lane >> 2;
    const int c    = lane & 3;

    float d[4][8][4];
#pragma unroll
    for (int mi = 0; mi < 4; mi++)
#pragma unroll
        for (int ni = 0; ni < 8; ni++)
#pragma unroll
            for (int j = 0; j < 4; j++) d[mi][ni][j] = 0.0f;

#pragma unroll 1
    for (int kt = 0; kt < NK; kt++) {
        cp_wait<1>();
        __syncthreads();

        if (kt + 2 < NK) load_stage(kt + 2, (kt + 2) % STAGES);
        cp_commit();   // uniform group counting

        const uint32_t* sa = reinterpret_cast<const uint32_t*>(
            smem + (size_t)(kt % STAGES) * STG_BYTES);
        const uint32_t* sb = sa + A_FLOATS;

#pragma unroll
        for (int ks = 0; ks < 4; ks++) {
            const int k = ks * 8;
            uint32_t a[4][4];
#pragma unroll
            for (int mi = 0; mi < 4; mi++) {
                const int row = wm + mi * 16 + r;
                a[mi][0] = sa[(size_t)row * SA_STRIDE + k + c];
                a[mi][1] = sa[(size_t)(row + 8) * SA_STRIDE + k + c];
                a[mi][2] = sa[(size_t)row * SA_STRIDE + k + c + 4];
                a[mi][3] = sa[(size_t)(row + 8) * SA_STRIDE + k + c + 4];
            }
            uint32_t b[8][2];
#pragma unroll
            for (int ni = 0; ni < 8; ni++) {
                const int col = wn + ni * 8 + r;
                b[ni][0] = sb[(size_t)(k + c) * SB_STRIDE + col];
                b[ni][1] = sb[(size_t)(k + c + 4) * SB_STRIDE + col];
            }
#pragma unroll
            for (int mi = 0; mi < 4; mi++)
#pragma unroll
                for (int ni = 0; ni < 8; ni++)
                    mma_tf32(d[mi][ni], a[mi], b[ni]);
        }
    }

    // epilogue: bias + relu + float2 stores
    const float* bias_s = smf + BIAS_OFF / 4 + wn;
#pragma unroll
    for (int mi = 0; mi < 4; mi++) {
#pragma unroll
        for (int rr = 0; rr < 2; rr++) {
            const int m = m0 + wm + mi * 16 + rr * 8 + r;
            float* op = out + ((size_t)batch * Sq + m) * Uo + n0 + wn;
#pragma unroll
            for (int ni = 0; ni < 8; ni++) {
                const int nl = ni * 8 + 2 * c;
                float2 v;
                v.x = fmaxf(d[mi][ni][2 * rr + 0] + bias_s[nl + 0], 0.0f);
                v.y = fmaxf(d[mi][ni][2 * rr + 1] + bias_s[nl + 1], 0.0f);
                *reinterpret_cast<float2*>(op + nl) = v;
            }
        }
    }
}

// ---------------- launch ----------------
extern "C" void kernel_launch(void* const* d_in, const int* in_sizes, int n_in,
                              void* d_out, int out_size) {
    const float* x     = (const float*)d_in[0];
    const float* ws    = (const float*)d_in[1];
    const float* bs    = (const float*)d_in[2];
    const int*   index = (const int*)d_in[3];
    float*       out   = (float*)d_out;
    (void)in_sizes; (void)n_in; (void)out_size;

    uint32_t* ws32_ptr = nullptr;
    uint32_t* x32_ptr  = nullptr;
    cudaGetSymbolAddress((void**)&ws32_ptr, g_ws32);
    cudaGetSymbolAddress((void**)&x32_ptr, g_x32);

    const size_t ws_n4 = (size_t)Ex * Dk * Uo / 4;
    const size_t x_n4  = (size_t)Bn * Sq * Dk / 4;
    cvt_tf32_kernel<<<8192, 256>>>((const float4*)ws, (uint4*)ws32_ptr, ws_n4);
    cvt_tf32_kernel<<<4096, 256>>>((const float4*)x, (uint4*)x32_ptr, x_n4);

    static bool attr_set = false;
    if (!attr_set) {
        cudaFuncSetAttribute(indexed_dense_gemm,
                             cudaFuncAttributeMaxDynamicSharedMemorySize, SMEM_REQ);
        attr_set = true;
    }

    indexed_dense_gemm<<<dim3(Uo / BN, Sq / BM, Bn), NTHREADS, SMEM_REQ>>>(bs, index, out);
}

// round 4
// speedup vs baseline: 1.8850x; 1.6644x over previous
#include <cuda_runtime.h>
#include <cuda_fp16.h>
#include <cstdint>
#include <cstddef>

// Problem constants
#define Bn 64
#define Sq 512
#define Dk 1024
#define Uo 4096
#define Ex 16

// Tiling: CTA 128x256, warp 64x64 (8 warps = 2m x 4n), 256 threads
#define BM 128
#define BN 256
#define BK 32
#define NK (Dk / BK)        // 32 K-tiles
#define NTHREADS 256
#define STAGES 4

// SMEM: halves, stride 40 per row (80 B) -> bank = (20*row + c) % 32, conflict-free
#define ST_H 40
#define A_TILE_B (BM * ST_H * 2)               // 10240
#define B_TILE_B (BN * ST_H * 2)               // 20480
#define STG_BYTES (A_TILE_B + B_TILE_B)        // 30720
#define BIAS_OFF (STAGES * STG_BYTES)          // 122880
#define SMEM_REQ (BIAS_OFF + BN * 4)           // 123904

// Device scratch: fp16 copies (x as-is, ws transposed to [e][n][k])
__device__ __half g_wsT[(size_t)Ex * Uo * Dk];   // 128 MB
__device__ __half g_x16[(size_t)Bn * Sq * Dk];   //  64 MB

// ---------------- helpers ----------------
__device__ __forceinline__ uint32_t smem_u32(const void* p) {
    uint32_t a;
    asm("{ .reg .u64 t; cvta.to.shared.u64 t, %1; cvt.u32.u64 %0, t; }"
        : "=r"(a) : "l"(p));
    return a;
}

__device__ __forceinline__ void cp16(uint32_t saddr, const void* g) {
    asm volatile("cp.async.cg.shared.global [%0], [%1], 16;" :: "r"(saddr), "l"(g));
}
__device__ __forceinline__ void cp_commit() {
    asm volatile("cp.async.commit_group;" ::: "memory");
}
template <int N>
__device__ __forceinline__ void cp_wait() {
    asm volatile("cp.async.wait_group %0;" :: "n"(N) : "memory");
}

__device__ __forceinline__ void mma_f16(float* d, const uint32_t* a, const uint32_t* b) {
    asm volatile(
        "mma.sync.aligned.m16n8k16.row.col.f32.f16.f16.f32 "
        "{%0,%1,%2,%3}, {%4,%5,%6,%7}, {%8,%9}, {%0,%1,%2,%3};"
        : "+f"(d[0]), "+f"(d[1]), "+f"(d[2]), "+f"(d[3])
        : "r"(a[0]), "r"(a[1]), "r"(a[2]), "r"(a[3]), "r"(b[0]), "r"(b[1]));
}

// ---------------- pre-pass 1: ws [e][k][n] fp32 -> g_wsT [e][n][k] fp16 ----------------
__global__ void __launch_bounds__(256) transpose_h_kernel(const float* __restrict__ ws) {
    __shared__ float tile[32][33];
    const int e  = blockIdx.z;
    const int k0 = blockIdx.y * 32;
    const int n0 = blockIdx.x * 32;
    const int tx = threadIdx.x;   // 0..31
    const int ty = threadIdx.y;   // 0..7

    const float* src = ws + ((size_t)e * Dk + k0) * Uo + n0;
#pragma unroll
    for (int j = 0; j < 4; j++)
        tile[ty + j * 8][tx] = src[(size_t)(ty + j * 8) * Uo + tx];   // tile[k][n]
    __syncthreads();

    __half* dst = g_wsT + ((size_t)e * Uo + n0) * Dk + k0;            // [n][k]
#pragma unroll
    for (int j = 0; j < 4; j++)
        dst[(size_t)(ty + j * 8) * Dk + tx] = __float2half_rn(tile[tx][ty + j * 8]);
}

// ---------------- pre-pass 2: x fp32 -> fp16 ----------------
__global__ void __launch_bounds__(256) cvt_h_kernel(const float4* __restrict__ src,
                                                    uint2* __restrict__ dst, size_t n4) {
    size_t i = (size_t)blockIdx.x * blockDim.x + threadIdx.x;
    size_t stride = (size_t)gridDim.x * blockDim.x;
    for (; i < n4; i += stride) {
        float4 v = src[i];
        __half2 lo = __floats2half2_rn(v.x, v.y);
        __half2 hi = __floats2half2_rn(v.z, v.w);
        uint2 o;
        o.x = *reinterpret_cast<uint32_t*>(&lo);
        o.y = *reinterpret_cast<uint32_t*>(&hi);
        dst[i] = o;
    }
}

// ---------------- main GEMM ----------------
__global__ void __launch_bounds__(NTHREADS)
indexed_dense_gemm(const float* __restrict__ bs, const int* __restrict__ index,
                   float* __restrict__ out) {
    extern __shared__ char smem[];
    const uint32_t sbase = smem_u32(smem);
    float* const smf = reinterpret_cast<float*>(smem);

    const int tid   = threadIdx.x;
    const int batch = blockIdx.z;
    const int m0    = blockIdx.y * BM;
    const int n0    = blockIdx.x * BN;
    const int e     = index[batch];

    // bias tile -> smem (256 floats, one per thread)
    smf[BIAS_OFF / 4 + tid] = bs[(size_t)e * Uo + n0 + tid];

    const __half* __restrict__ xg = g_x16 + ((size_t)batch * Sq + m0) * Dk;  // [m][k]
    const __half* __restrict__ wg = g_wsT + ((size_t)e * Uo + n0) * Dk;      // [n][k]

    // cp.async coordinates: 16B chunks of 8 halves; rows have 4 chunks (64 B of k)
    const int ar  = tid >> 2;          // A row 0..63 (two passes cover 128)
    const int ac4 = tid & 3;           // chunk in row
    const uint32_t a_s0 = sbase + (uint32_t)(ar * 80 + ac4 * 16);
    const uint32_t b_s0 = sbase + A_TILE_B + (uint32_t)(ar * 80 + ac4 * 16);

    auto load_stage = [&](int kt, int s) {
        const uint32_t so = (uint32_t)s * STG_BYTES;
        const __half* ag = xg + (size_t)ar * Dk + kt * BK + ac4 * 8;
        const __half* bg = wg + (size_t)ar * Dk + kt * BK + ac4 * 8;
        // A: 128 rows, 64 rows per pass
#pragma unroll
        for (int j = 0; j < 2; j++)
            cp16(a_s0 + so + j * 64 * 80, ag + (size_t)j * 64 * Dk);
        // B: 256 rows, 64 per pass
#pragma unroll
        for (int j = 0; j < 4; j++)
            cp16(b_s0 + so + j * 64 * 80, bg + (size_t)j * 64 * Dk);
    };

    // prologue: stages 0..2
    load_stage(0, 0); cp_commit();
    load_stage(1, 1); cp_commit();
    load_stage(2, 2); cp_commit();

    // warp tiling: 8 warps = 2 (m) x 4 (n); warp tile 64 x 64
    const int warp = tid >> 5;
    const int lane = tid & 31;
    const int wm   = (warp >> 2) * 64;
    const int wn   = (warp & 3) * 64;
    const int r    = lane >> 2;
    const int c    = lane & 3;

    float d[4][8][4];
#pragma unroll
    for (int mi = 0; mi < 4; mi++)
#pragma unroll
        for (int ni = 0; ni < 8; ni++)
#pragma unroll
            for (int j = 0; j < 4; j++) d[mi][ni][j] = 0.0f;

#pragma unroll 1
    for (int kt = 0; kt < NK; kt++) {
        cp_wait<2>();
        __syncthreads();

        if (kt + 3 < NK) load_stage(kt + 3, (kt + 3) & (STAGES - 1));
        cp_commit();   // uniform group counting

        const __half* sa = reinterpret_cast<const __half*>(
            smem + (size_t)(kt & (STAGES - 1)) * STG_BYTES);
        const __half* sb = sa + BM * ST_H;

#pragma unroll
        for (int ks = 0; ks < 2; ks++) {
            const int k = ks * 16;
            uint32_t a[4][4];
#pragma unroll
            for (int mi = 0; mi < 4; mi++) {
                const int row = wm + mi * 16 + r;
                a[mi][0] = *reinterpret_cast<const uint32_t*>(&sa[(size_t)row * ST_H + k + 2 * c]);
                a[mi][1] = *reinterpret_cast<const uint32_t*>(&sa[(size_t)(row + 8) * ST_H + k + 2 * c]);
                a[mi][2] = *reinterpret_cast<const uint32_t*>(&sa[(size_t)row * ST_H + k + 2 * c + 8]);
                a[mi][3] = *reinterpret_cast<const uint32_t*>(&sa[(size_t)(row + 8) * ST_H + k + 2 * c + 8]);
            }
            uint32_t b[8][2];
#pragma unroll
            for (int ni = 0; ni < 8; ni++) {
                const int col = wn + ni * 8 + r;
                b[ni][0] = *reinterpret_cast<const uint32_t*>(&sb[(size_t)col * ST_H + k + 2 * c]);
                b[ni][1] = *reinterpret_cast<const uint32_t*>(&sb[(size_t)col * ST_H + k + 2 * c + 8]);
            }
#pragma unroll
            for (int mi = 0; mi < 4; mi++)
#pragma unroll
                for (int ni = 0; ni < 8; ni++)
                    mma_f16(d[mi][ni], a[mi], b[ni]);
        }
    }

    // epilogue: bias + relu + float2 stores
    const float* bias_s = smf + BIAS_OFF / 4 + wn;
#pragma unroll
    for (int mi = 0; mi < 4; mi++) {
#pragma unroll
        for (int rr = 0; rr < 2; rr++) {
            const int m = m0 + wm + mi * 16 + rr * 8 + r;
            float* op = out + ((size_t)batch * Sq + m) * Uo + n0 + wn;
#pragma unroll
            for (int ni = 0; ni < 8; ni++) {
                const int nl = ni * 8 + 2 * c;
                float2 v;
                v.x = fmaxf(d[mi][ni][2 * rr + 0] + bias_s[nl + 0], 0.0f);
                v.y = fmaxf(d[mi][ni][2 * rr + 1] + bias_s[nl + 1], 0.0f);
                *reinterpret_cast<float2*>(op + nl) = v;
            }
        }
    }
}

// ---------------- launch ----------------
extern "C" void kernel_launch(void* const* d_in, const int* in_sizes, int n_in,
                              void* d_out, int out_size) {
    const float* x     = (const float*)d_in[0];
    const float* ws    = (const float*)d_in[1];
    const float* bs    = (const float*)d_in[2];
    const int*   index = (const int*)d_in[3];
    float*       out   = (float*)d_out;
    (void)in_sizes; (void)n_in; (void)out_size;

    __half* x16_ptr = nullptr;
    cudaGetSymbolAddress((void**)&x16_ptr, g_x16);

    // pre-pass: ws transpose+cvt, x cvt
    transpose_h_kernel<<<dim3(Uo / 32, Dk / 32, Ex), dim3(32, 8)>>>(ws);
    const size_t x_n4 = (size_t)Bn * Sq * Dk / 4;
    cvt_h_kernel<<<4096, 256>>>((const float4*)x, (uint2*)x16_ptr, x_n4);

    static bool attr_set = false;
    if (!attr_set) {
        cudaFuncSetAttribute(indexed_dense_gemm,
                             cudaFuncAttributeMaxDynamicSharedMemorySize, SMEM_REQ);
        attr_set = true;
    }

    indexed_dense_gemm<<<dim3(Uo / BN, Sq / BM, Bn), NTHREADS, SMEM_REQ>>>(bs, index, out);
}